// round 2
// baseline (speedup 1.0000x reference)
#include <cuda_runtime.h>
#include <math.h>

#define BT 256   // threads per block (main kernel)
#define M  8     // batch rows per block

// ---------------- problem constants ----------------
constexpr int Bsz = 1024, Tsz = 256, DIN = 128;
constexpr int NH0 = 269, NH1 = 179, NH2 = 64;
constexpr int CAT0 = DIN + NH0;   // 397
constexpr int CAT1 = NH0 + NH1;   // 448
constexpr int CAT2 = NH1 + NH2;   // 243
constexpr int CATP0 = 400, CATP1 = 448, CATP2 = 244;  // padded to mult of 4
constexpr int NO0 = 4 * NH0;      // 1076 (gates folded into output dim)
constexpr int NO1 = 4 * NH1;      // 716
constexpr int NO2 = 4 * NH2;      // 256
constexpr int XCS0 = CATP0, XCS1 = CATP1, XCS2 = CATP2;
constexpr int OUTD = 64;
constexpr long long PRED_ELEMS = (long long)Bsz * Tsz * OUTD;

// ---------------- device scratch (no runtime alloc allowed) ----------------
__device__ float g_WT0[CATP0 * NO0];
__device__ float g_WT1[CATP1 * NO1];
__device__ float g_WT2[CATP2 * NO2];
__device__ float g_bC0[NO0];
__device__ float g_bC1[NO1];
__device__ float g_bC2[NO2];
__device__ int   g_fmt[3];

// ---------------- mask dtype detection ----------------
// We only know element counts, not byte sizes. Reading n_elem BYTES is safe for
// every candidate dtype (u8 buffer is exactly n bytes; wider dtypes are larger).
// Classify from 32-bit word patterns over those bytes.
__global__ void detect_kernel(const void* m0, int n0, const void* m1, int n1,
                              const void* m2, int n2) {
    const void* p = (blockIdx.x == 0) ? m0 : (blockIdx.x == 1) ? m1 : m2;
    int n = (blockIdx.x == 0) ? n0 : (blockIdx.x == 1) ? n1 : n2;
    __shared__ int fl;
    if (threadIdx.x == 0) fl = 0;
    __syncthreads();
    int nw = n >> 2;
    const unsigned* w = (const unsigned*)p;
    int loc = 0;
    for (int i = threadIdx.x; i < nw; i += blockDim.x) {
        unsigned v = w[i];
        if (v == 0x3F800000u) loc |= 1;                       // fp32 1.0
        else if (v == 0x3F803F80u || v == 0x00003F80u) loc |= 2; // bf16 pair with a 1.0
        else if (v != 0u && v != 1u) loc |= 4;                // packed bytes -> u8
    }
    atomicOr(&fl, loc);
    __syncthreads();
    if (threadIdx.x == 0) {
        int f = fl, fmt;
        if (f & 2) fmt = 3;       // bf16
        else if (f & 1) fmt = 0;  // float32
        else if (f & 4) fmt = 2;  // uint8
        else fmt = 1;             // int32 (all words 0/1)
        g_fmt[blockIdx.x] = fmt;
    }
}

__device__ __forceinline__ bool maskbit(const void* p, int fmt, int idx) {
    switch (fmt) {
        case 0: return ((const float*)p)[idx] != 0.0f;
        case 1: return ((const int*)p)[idx] != 0;
        case 3: return ((const unsigned short*)p)[idx] != 0;
        default: return ((const unsigned char*)p)[idx] != 0;
    }
}

// ---------------- weight transpose + mask preprocessing ----------------
// Source weights: W[j][k], j in [0,NH), k in [0,CAT) row-major.
// Dest: WT[k][g*NH + j] with k padded to CATP (pad rows zero). Masks apply to
// gates 0 (ff1) and 1 (ff2) only. Bias folded into biasC[g*NH+j].
__global__ void prep_kernel(const float* __restrict__ w1, const float* __restrict__ w2,
                            const float* __restrict__ wa, const float* __restrict__ wb,
                            const float* __restrict__ b1, const float* __restrict__ b2,
                            const float* __restrict__ ba, const float* __restrict__ bb,
                            const void* mask, int fmtIdx,
                            int CAT, int CATP, int NH,
                            float* __restrict__ WT, float* __restrict__ biasC) {
    int fmt = g_fmt[fmtIdx];
    int NO = 4 * NH;
    long long total = (long long)CATP * NO;
    for (long long idx = (long long)blockIdx.x * blockDim.x + threadIdx.x;
         idx < total; idx += (long long)gridDim.x * blockDim.x) {
        int k = (int)(idx / NO);
        int o = (int)(idx - (long long)k * NO);
        int g = o / NH;
        int j = o - g * NH;
        float v = 0.0f;
        if (k < CAT) {
            const float* ws = (g == 0) ? w1 : (g == 1) ? w2 : (g == 2) ? wa : wb;
            v = ws[j * CAT + k];
            if (g < 2) {
                if (!maskbit(mask, fmt, j * CAT + k)) v = 0.0f;
            }
        }
        WT[idx] = v;
        if (k == 0) {
            const float* bs = (g == 0) ? b1 : (g == 1) ? b2 : (g == 2) ? ba : bb;
            biasC[o] = bs[j];
        }
    }
}

// ---------------- main persistent kernel ----------------
struct SM {
    float xc0[M][XCS0];   // [ x_t (128) | h0 (269) | pad(3) ]
    float xc1[M][XCS1];   // [ n0 (269)  | h1 (179) ]
    float xc2[M][XCS2];   // [ n1 (179)  | h2 (64) | pad(1) ]
    float G[M][NO0];      // gate pre-activations (max layer size)
    float fcT[OUTD * OUTD]; // fc_w transposed: fcT[m*64+o] = fc_w[o][m]
    float fcb[OUTD];
    float b0[NO0];
    float b1[NO1];
    float b2[NO2];
};

// GEMM: out[g*NH+j] = bias + sum_k XC[r][k] * WT[k][g*NH+j], for all M rows.
// Thread handles 4 consecutive outputs (LDG.128 weights), all M rows in regs.
// xc loads are warp-broadcast LDS.128 (conflict-free).
template <int CATP, int NOUT, int XCS>
__device__ __forceinline__ void gemm_gates(const float* __restrict__ WT,
                                           const float* __restrict__ biasS,
                                           const float* __restrict__ XC,
                                           float* __restrict__ G) {
    const int tid = threadIdx.x;
    for (int obase = 0; obase < NOUT; obase += BT * 4) {
        int o0 = obase + tid * 4;
        if (o0 >= NOUT) break;  // NOUT is a multiple of 4, so o0..o0+3 valid
        float4 bv = *(const float4*)&biasS[o0];
        float acc[M][4];
#pragma unroll
        for (int r = 0; r < M; ++r) {
            acc[r][0] = bv.x; acc[r][1] = bv.y; acc[r][2] = bv.z; acc[r][3] = bv.w;
        }
        const float* wp = WT + o0;
#pragma unroll 2
        for (int k = 0; k < CATP; k += 4) {
            float4 xv[M];
#pragma unroll
            for (int r = 0; r < M; ++r)
                xv[r] = *(const float4*)&XC[r * XCS + k];
            float4 w0 = __ldg((const float4*)(wp + (long long)(k + 0) * NOUT));
            float4 w1 = __ldg((const float4*)(wp + (long long)(k + 1) * NOUT));
            float4 w2 = __ldg((const float4*)(wp + (long long)(k + 2) * NOUT));
            float4 w3 = __ldg((const float4*)(wp + (long long)(k + 3) * NOUT));
#pragma unroll
            for (int r = 0; r < M; ++r) {
                float xk;
                xk = xv[r].x;
                acc[r][0] += w0.x * xk; acc[r][1] += w0.y * xk;
                acc[r][2] += w0.z * xk; acc[r][3] += w0.w * xk;
                xk = xv[r].y;
                acc[r][0] += w1.x * xk; acc[r][1] += w1.y * xk;
                acc[r][2] += w1.z * xk; acc[r][3] += w1.w * xk;
                xk = xv[r].z;
                acc[r][0] += w2.x * xk; acc[r][1] += w2.y * xk;
                acc[r][2] += w2.z * xk; acc[r][3] += w2.w * xk;
                xk = xv[r].w;
                acc[r][0] += w3.x * xk; acc[r][1] += w3.y * xk;
                acc[r][2] += w3.z * xk; acc[r][3] += w3.w * xk;
            }
        }
#pragma unroll
        for (int r = 0; r < M; ++r) {
            float4 v = make_float4(acc[r][0], acc[r][1], acc[r][2], acc[r][3]);
            *(float4*)&G[r * NOUT + o0] = v;
        }
    }
}

// CfC cell combine: n = tanh(ff1)*(1-s) + s*tanh(ff2), s = sigmoid(ta+tb)
template <int NOUT, int NH>
__device__ __forceinline__ void combine_gates(const float* __restrict__ G,
                                              float* __restrict__ dA, int sA, int oA,
                                              float* __restrict__ dB, int sB, int oB) {
    for (int j = threadIdx.x; j < NH; j += BT) {
#pragma unroll
        for (int r = 0; r < M; ++r) {
            const float* g = G + r * NOUT;
            float f1 = g[j];
            float f2 = g[NH + j];
            float ga = g[2 * NH + j];
            float gb = g[3 * NH + j];
            float s = 1.0f / (1.0f + __expf(-(ga + gb)));
            float n = tanhf(f1) * (1.0f - s) + s * tanhf(f2);
            dA[r * sA + oA + j] = n;
            dB[r * sB + oB + j] = n;
        }
    }
}

__global__ __launch_bounds__(BT, 1)
void ncp_main(const float* __restrict__ x, const float* __restrict__ hidden,
              const float* __restrict__ fc_w, const float* __restrict__ fc_b,
              float* __restrict__ out) {
    extern __shared__ char smem_raw[];
    SM* sm = (SM*)smem_raw;
    const int tid = threadIdx.x;
    const int row0 = blockIdx.x * M;

    // ---- init: biases, fc weights (transposed), hidden state, zero pads ----
    for (int i = tid; i < NO0; i += BT) sm->b0[i] = g_bC0[i];
    for (int i = tid; i < NO1; i += BT) sm->b1[i] = g_bC1[i];
    for (int i = tid; i < NO2; i += BT) sm->b2[i] = g_bC2[i];
    for (int i = tid; i < OUTD * OUTD; i += BT) {
        int mm = i >> 6, o = i & 63;
        sm->fcT[i] = __ldg(&fc_w[o * OUTD + mm]);
    }
    if (tid < OUTD) sm->fcb[tid] = fc_b[tid];
    for (int i = tid; i < M * 512; i += BT) {
        int r = i >> 9, c = i & 511;
        float v = hidden[(long long)(row0 + r) * 512 + c];
        if (c < NH0)              sm->xc0[r][DIN + c] = v;
        else if (c < NH0 + NH1)   sm->xc1[r][c] = v;              // NH0 + (c-NH0)
        else                      sm->xc2[r][NH1 + (c - NH0 - NH1)] = v;
    }
    if (tid < M) {
        sm->xc0[tid][397] = 0.0f; sm->xc0[tid][398] = 0.0f; sm->xc0[tid][399] = 0.0f;
        sm->xc2[tid][243] = 0.0f;
    }
    __syncthreads();

    // ---- sequential timestep loop ----
    for (int t = 0; t < Tsz; ++t) {
        // load x_t rows: one float4 per thread (256 threads = 8 rows x 32 f4)
        {
            int r = tid >> 5, c4 = (tid & 31) << 2;
            const float* xp = x + ((long long)(row0 + r) * Tsz + t) * DIN + c4;
            *(float4*)&sm->xc0[r][c4] = __ldg((const float4*)xp);
        }
        __syncthreads();

        gemm_gates<CATP0, NO0, XCS0>(g_WT0, sm->b0, &sm->xc0[0][0], &sm->G[0][0]);
        __syncthreads();
        // n0 -> layer1 input AND next h0
        combine_gates<NO0, NH0>(&sm->G[0][0],
                                &sm->xc1[0][0], XCS1, 0,
                                &sm->xc0[0][0], XCS0, DIN);
        __syncthreads();

        gemm_gates<CATP1, NO1, XCS1>(g_WT1, sm->b1, &sm->xc1[0][0], &sm->G[0][0]);
        __syncthreads();
        // n1 -> layer2 input AND next h1
        combine_gates<NO1, NH1>(&sm->G[0][0],
                                &sm->xc2[0][0], XCS2, 0,
                                &sm->xc1[0][0], XCS1, NH0);
        __syncthreads();

        gemm_gates<CATP2, NO2, XCS2>(g_WT2, sm->b2, &sm->xc2[0][0], &sm->G[0][0]);
        __syncthreads();
        // n2 -> next h2 (also the motor output)
        combine_gates<NO2, NH2>(&sm->G[0][0],
                                &sm->xc2[0][0], XCS2, NH1,
                                &sm->xc2[0][0], XCS2, NH1);
        __syncthreads();

        // fused output projection: pred[b,t,o] = fc_b[o] + sum_m n2[m]*fc_w[o][m]
        for (int idx = tid; idx < M * OUTD; idx += BT) {
            int r = idx >> 6, o = idx & 63;
            float a = sm->fcb[o];
            const float* n2 = &sm->xc2[r][NH1];
#pragma unroll 8
            for (int mm = 0; mm < OUTD; ++mm)
                a += sm->fcT[mm * OUTD + o] * n2[mm];
            out[((long long)(row0 + r) * Tsz + t) * OUTD + o] = a;
        }
        // no sync needed: next phase writes xc0 x-part only, then syncs
    }
    __syncthreads();

    // ---- final hidden state hn = [h0|h1|h2] at offset PRED_ELEMS ----
    float* hn = out + PRED_ELEMS;
    for (int i = tid; i < M * 512; i += BT) {
        int r = i >> 9, c = i & 511;
        float v;
        if (c < NH0)            v = sm->xc0[r][DIN + c];
        else if (c < NH0 + NH1) v = sm->xc1[r][c];
        else                    v = sm->xc2[r][NH1 + (c - NH0 - NH1)];
        hn[(long long)(row0 + r) * 512 + c] = v;
    }
}

// ---------------- host launcher ----------------
extern "C" void kernel_launch(void* const* d_in, const int* in_sizes, int n_in,
                              void* d_out, int out_size) {
    (void)n_in; (void)out_size;
    const float* x      = (const float*)d_in[0];
    const float* hidden = (const float*)d_in[1];
    const void*  m0     = d_in[2];
    const void*  m1     = d_in[3];
    const void*  m2     = d_in[4];
    const float* ff1_w0 = (const float*)d_in[5];
    const float* ff1_b0 = (const float*)d_in[6];
    const float* ff2_w0 = (const float*)d_in[7];
    const float* ff2_b0 = (const float*)d_in[8];
    const float* ta_w0  = (const float*)d_in[9];
    const float* ta_b0  = (const float*)d_in[10];
    const float* tb_w0  = (const float*)d_in[11];
    const float* tb_b0  = (const float*)d_in[12];
    const float* ff1_w1 = (const float*)d_in[13];
    const float* ff1_b1 = (const float*)d_in[14];
    const float* ff2_w1 = (const float*)d_in[15];
    const float* ff2_b1 = (const float*)d_in[16];
    const float* ta_w1  = (const float*)d_in[17];
    const float* ta_b1  = (const float*)d_in[18];
    const float* tb_w1  = (const float*)d_in[19];
    const float* tb_b1  = (const float*)d_in[20];
    const float* ff1_w2 = (const float*)d_in[21];
    const float* ff1_b2 = (const float*)d_in[22];
    const float* ff2_w2 = (const float*)d_in[23];
    const float* ff2_b2 = (const float*)d_in[24];
    const float* ta_w2  = (const float*)d_in[25];
    const float* ta_b2  = (const float*)d_in[26];
    const float* tb_w2  = (const float*)d_in[27];
    const float* tb_b2  = (const float*)d_in[28];
    const float* fc_w   = (const float*)d_in[29];
    const float* fc_b   = (const float*)d_in[30];
    float* out = (float*)d_out;

    // resolve __device__ symbols for prep kernel destinations
    float *wt0, *wt1, *wt2, *bc0, *bc1, *bc2;
    cudaGetSymbolAddress((void**)&wt0, g_WT0);
    cudaGetSymbolAddress((void**)&wt1, g_WT1);
    cudaGetSymbolAddress((void**)&wt2, g_WT2);
    cudaGetSymbolAddress((void**)&bc0, g_bC0);
    cudaGetSymbolAddress((void**)&bc1, g_bC1);
    cudaGetSymbolAddress((void**)&bc2, g_bC2);

    detect_kernel<<<3, 256>>>(m0, in_sizes[2], m1, in_sizes[3], m2, in_sizes[4]);

    int blocks0 = (CATP0 * NO0 + 255) / 256;
    int blocks1 = (CATP1 * NO1 + 255) / 256;
    int blocks2 = (CATP2 * NO2 + 255) / 256;
    prep_kernel<<<blocks0, 256>>>(ff1_w0, ff2_w0, ta_w0, tb_w0,
                                  ff1_b0, ff2_b0, ta_b0, tb_b0,
                                  m0, 0, CAT0, CATP0, NH0, wt0, bc0);
    prep_kernel<<<blocks1, 256>>>(ff1_w1, ff2_w1, ta_w1, tb_w1,
                                  ff1_b1, ff2_b1, ta_b1, tb_b1,
                                  m1, 1, CAT1, CATP1, NH1, wt1, bc1);
    prep_kernel<<<blocks2, 256>>>(ff1_w2, ff2_w2, ta_w2, tb_w2,
                                  ff1_b2, ff2_b2, ta_b2, tb_b2,
                                  m2, 2, CAT2, CATP2, NH2, wt2, bc2);

    cudaFuncSetAttribute(ncp_main, cudaFuncAttributeMaxDynamicSharedMemorySize,
                         (int)sizeof(SM));
    ncp_main<<<Bsz / M, BT, sizeof(SM)>>>(x, hidden, fc_w, fc_b, out);
}